// round 8
// baseline (speedup 1.0000x reference)
#include <cuda_runtime.h>
#include <cstdint>

// LearnableFiltration via mma.sync tf32 (sm_103 family target: no tcgen05).
// out[b,i,j] = softplus( relu( relu(H1) @ W2 + b2 ) @ W3 + b3 )
// H1[j,h] = wi*W1[0,h] + wj*W1[1,h] + d_ij*W1[2,h] + b1[h];  B=4,N=1024,H=32.
//
// R8 = R7 (2x 16-row tiles, kt-interleaved) with register diet:
//   W1 columns reloaded per-kt from smem (LDS.128, immediate offsets) instead
//   of 32 persistent regs; ai folded into the kt loop (no array). Target
//   regs <= 128 -> 4 CTAs/SM; GRID 444 -> 592.

#define NB    4
#define NN    1024
#define NH    32
#define TPB   128                        // 4 warps / block
#define GRID  592                        // 4 blocks/SM * 148 SMs
#define NWT2  (NB * NN * (NN / 32))      // 131072 warp-tiles of 32 j's

static __device__ __forceinline__ uint32_t to_tf32(float x) {
    uint32_t r;
    asm("cvt.rna.tf32.f32 %0, %1;" : "=r"(r) : "f"(x));
    return r;
}

// D += A*B (in-place accumulate)
static __device__ __forceinline__ void mma_acc(float* d, const uint32_t* a,
                                               const uint32_t* b) {
    asm volatile(
        "mma.sync.aligned.m16n8k8.row.col.f32.tf32.tf32.f32 "
        "{%0,%1,%2,%3}, {%4,%5,%6,%7}, {%8,%9}, {%0,%1,%2,%3};"
        : "+f"(d[0]), "+f"(d[1]), "+f"(d[2]), "+f"(d[3])
        : "r"(a[0]), "r"(a[1]), "r"(a[2]), "r"(a[3]), "r"(b[0]), "r"(b[1]));
}
// D = A*B + {c0,c1,c0,c1}  (bias init: writes D fresh)
static __device__ __forceinline__ void mma_bias(float* d, const uint32_t* a,
                                                const uint32_t* b,
                                                float c0, float c1) {
    asm volatile(
        "mma.sync.aligned.m16n8k8.row.col.f32.tf32.tf32.f32 "
        "{%0,%1,%2,%3}, {%4,%5,%6,%7}, {%8,%9}, {%10,%11,%10,%11};"
        : "=f"(d[0]), "=f"(d[1]), "=f"(d[2]), "=f"(d[3])
        : "r"(a[0]), "r"(a[1]), "r"(a[2]), "r"(a[3]), "r"(b[0]), "r"(b[1]),
          "f"(c0), "f"(c1));
}

// softplus(x) = max(x,0) + ln2 * lg2(1 + 2^(-|x|*log2e)), MUFU approx
static __device__ __forceinline__ float softplus_fast(float x) {
    float t, l;
    const float nax = -fabsf(x) * 1.442695041f;
    asm("ex2.approx.f32 %0, %1;" : "=f"(t) : "f"(nax));
    asm("lg2.approx.f32 %0, %1;" : "=f"(l) : "f"(t + 1.0f));
    return fmaxf(x, 0.0f) + 0.693147181f * l;
}

__global__ void __launch_bounds__(TPB)
lf_mma8_kernel(const float* __restrict__ weights,
               const float* __restrict__ distances,
               const float* __restrict__ W1,
               const float* __restrict__ b1,
               const float* __restrict__ W2,
               const float* __restrict__ b2,
               const float* __restrict__ W3,
               const float* __restrict__ b3,
               float* __restrict__ out)
{
    __shared__ float  sW[NB * NN];    // all weights (16 KB)
    __shared__ float4 sW1[NH];        // {W1[0,h], W1[1,h], W1[2,h], b1[h]}
    __shared__ float2 sBW[NH];        // {b2[k], W3[k]}
    __shared__ float  sW2[NH * NH];   // W2[h][n] row-major

    const int tid  = threadIdx.x;
    const int wid  = tid >> 5;
    const int lane = tid & 31;
    const int q    = lane & 3;        // k / col position in quad
    const int g    = lane >> 2;       // row position

    for (int x = tid; x < (NB * NN) / 4; x += TPB)
        ((float4*)sW)[x] = ((const float4*)weights)[x];
    for (int x = tid; x < (NH * NH) / 4; x += TPB)
        ((float4*)sW2)[x] = ((const float4*)W2)[x];
    if (tid < NH) {
        sW1[tid] = make_float4(W1[tid], W1[NH + tid], W1[2 * NH + tid], b1[tid]);
        sBW[tid] = make_float2(b2[tid], W3[tid]);
    }
    __syncthreads();

    // ---- loop-invariant register state ----
    uint32_t bf[4][4][2];             // W2^T fragments (tf32), 32 regs
#pragma unroll
    for (int kt = 0; kt < 4; kt++)
#pragma unroll
        for (int nt = 0; nt < 4; nt++) {
            bf[kt][nt][0] = to_tf32(sW2[(kt * 8 + q) * NH + nt * 8 + g]);
            bf[kt][nt][1] = to_tf32(sW2[(kt * 8 + q + 4) * NH + nt * 8 + g]);
        }
    float2 bw[8];                     // {b2, W3} at n = 8nt + 2q + {0,1}
#pragma unroll
    for (int nt = 0; nt < 4; nt++) {
        bw[2 * nt]     = sBW[8 * nt + 2 * q];
        bw[2 * nt + 1] = sBW[8 * nt + 2 * q + 1];
    }
    const float b3v = b3[0];
    const float4* w1q = &sW1[q];      // base pointer; per-kt immediate offsets

    const int gw     = blockIdx.x * 4 + wid;
    const int stride = GRID * 4;

    // prefetch first tile's distances (flat elem offset = t*32 + g)
    float d0 = 0.f, d1 = 0.f, d2 = 0.f, d3 = 0.f;
    if (gw < NWT2) {
        const unsigned off = ((unsigned)gw << 5) + g;
        d0 = __ldcs(distances + off);
        d1 = __ldcs(distances + off + 8);
        d2 = __ldcs(distances + off + 16);
        d3 = __ldcs(distances + off + 24);
    }

    for (int t = gw; t < NWT2; t += stride) {
        const unsigned off = ((unsigned)t << 5) + g;

        const float wi = sW[t >> 5];
        const unsigned jbase = ((unsigned)(t >> 15) << 10) + ((t & 31) << 5) + g;
        const float wj0 = sW[jbase];
        const float wj1 = sW[jbase + 8];
        const float wj2 = sW[jbase + 16];
        const float wj3 = sW[jbase + 24];

        float accA[4][4], accB[4][4];

        // ---- kt-interleaved: reload W1 cols, build 8 A-frags, fire 8 MMAs ----
#pragma unroll
        for (int kt = 0; kt < 4; kt++) {
            const float4 cA = w1q[8 * kt];        // col q + 8kt
            const float4 cB = w1q[8 * kt + 4];    // col q + 4 + 8kt
            const float aA = fmaf(cA.x, wi, cA.w);
            const float aB = fmaf(cB.x, wi, cB.w);
            uint32_t afA[4], afB[4];
            afA[0] = __float_as_uint(fmaxf(fmaf(cA.z, d0, fmaf(cA.y, wj0, aA)), 0.f));
            afA[1] = __float_as_uint(fmaxf(fmaf(cA.z, d1, fmaf(cA.y, wj1, aA)), 0.f));
            afA[2] = __float_as_uint(fmaxf(fmaf(cB.z, d0, fmaf(cB.y, wj0, aB)), 0.f));
            afA[3] = __float_as_uint(fmaxf(fmaf(cB.z, d1, fmaf(cB.y, wj1, aB)), 0.f));
            afB[0] = __float_as_uint(fmaxf(fmaf(cA.z, d2, fmaf(cA.y, wj2, aA)), 0.f));
            afB[1] = __float_as_uint(fmaxf(fmaf(cA.z, d3, fmaf(cA.y, wj3, aA)), 0.f));
            afB[2] = __float_as_uint(fmaxf(fmaf(cB.z, d2, fmaf(cB.y, wj2, aB)), 0.f));
            afB[3] = __float_as_uint(fmaxf(fmaf(cB.z, d3, fmaf(cB.y, wj3, aB)), 0.f));

            if (kt == 0) {
#pragma unroll
                for (int nt = 0; nt < 4; nt++) {
                    mma_bias(accA[nt], afA, bf[0][nt], bw[2*nt].x, bw[2*nt+1].x);
                    mma_bias(accB[nt], afB, bf[0][nt], bw[2*nt].x, bw[2*nt+1].x);
                }
            } else {
#pragma unroll
                for (int nt = 0; nt < 4; nt++) {
                    mma_acc(accA[nt], afA, bf[kt][nt]);
                    mma_acc(accB[nt], afB, bf[kt][nt]);
                }
            }
        }

        // prefetch next tile (hide LDG under epilogue)
        const int tn = t + stride;
        float d0n = 0.f, d1n = 0.f, d2n = 0.f, d3n = 0.f;
        if (tn < NWT2) {
            const unsigned offn = ((unsigned)tn << 5) + g;
            d0n = __ldcs(distances + offn);
            d1n = __ldcs(distances + offn + 8);
            d2n = __ldcs(distances + offn + 16);
            d3n = __ldcs(distances + offn + 24);
        }

        // ---- epilogue: relu . W3, quad reduce, softplus ----
        float s0 = 0.f, s1 = 0.f, s2 = 0.f, s3 = 0.f;
#pragma unroll
        for (int nt = 0; nt < 4; nt++) {
            const float w30 = bw[2 * nt].y;
            const float w31 = bw[2 * nt + 1].y;
            s0 = fmaf(fmaxf(accA[nt][0], 0.f), w30, s0);
            s0 = fmaf(fmaxf(accA[nt][1], 0.f), w31, s0);
            s1 = fmaf(fmaxf(accA[nt][2], 0.f), w30, s1);
            s1 = fmaf(fmaxf(accA[nt][3], 0.f), w31, s1);
            s2 = fmaf(fmaxf(accB[nt][0], 0.f), w30, s2);
            s2 = fmaf(fmaxf(accB[nt][1], 0.f), w31, s2);
            s3 = fmaf(fmaxf(accB[nt][2], 0.f), w30, s3);
            s3 = fmaf(fmaxf(accB[nt][3], 0.f), w31, s3);
        }
        s0 += __shfl_xor_sync(0xffffffffu, s0, 1);
        s1 += __shfl_xor_sync(0xffffffffu, s1, 1);
        s2 += __shfl_xor_sync(0xffffffffu, s2, 1);
        s3 += __shfl_xor_sync(0xffffffffu, s3, 1);
        s0 += __shfl_xor_sync(0xffffffffu, s0, 2);
        s1 += __shfl_xor_sync(0xffffffffu, s1, 2);
        s2 += __shfl_xor_sync(0xffffffffu, s2, 2);
        s3 += __shfl_xor_sync(0xffffffffu, s3, 2);

        if (q == 0) {
            __stcs(out + off,      softplus_fast(s0 + b3v));
            __stcs(out + off + 8,  softplus_fast(s1 + b3v));
            __stcs(out + off + 16, softplus_fast(s2 + b3v));
            __stcs(out + off + 24, softplus_fast(s3 + b3v));
        }

        d0 = d0n; d1 = d1n; d2 = d2n; d3 = d3n;
    }
}

extern "C" void kernel_launch(void* const* d_in, const int* in_sizes, int n_in,
                              void* d_out, int out_size)
{
    const float* weights   = (const float*)d_in[0];
    const float* distances = (const float*)d_in[1];
    const float* W1        = (const float*)d_in[2];
    const float* b1        = (const float*)d_in[3];
    const float* W2        = (const float*)d_in[4];
    const float* b2        = (const float*)d_in[5];
    const float* W3        = (const float*)d_in[6];
    const float* b3        = (const float*)d_in[7];
    float* out             = (float*)d_out;

    lf_mma8_kernel<<<GRID, TPB>>>(weights, distances, W1, b1, W2, b2, W3, b3, out);
}

// round 9
// speedup vs baseline: 1.2380x; 1.2380x over previous
#include <cuda_runtime.h>
#include <cstdint>

// LearnableFiltration via mma.sync bf16 m16n8k16 (sm_103 family target).
// out[b,i,j] = softplus( relu( relu(H1) @ W2 + b2 ) @ W3 + b3 )
// H1[j,h] = wi*W1[0,h] + wj*W1[1,h] + d_ij*W1[2,h] + b1[h];  B=4,N=1024,H=32.
//
// R9: bf16 K=16 MMAs (16 HMMA/tile, 2-deep chains, half tensor time) and
// packed fma.rn.f32x2 layer-1 (A-frag reg = 2 FFMA2 + 2 FMNMX + 1 cvt.bf16x2).
// R7 config otherwise: persistent regs, GRID=444, bias-in-C, fast softplus.

#define NB    4
#define NN    1024
#define NH    32
#define TPB   128                        // 4 warps / block
#define GRID  444                        // 3 blocks/SM * 148 SMs
#define NWT2  (NB * NN * (NN / 32))      // 131072 warp-tiles of 32 j's

typedef unsigned long long ull;

static __device__ __forceinline__ ull pack2(float lo, float hi) {
    ull r;
    asm("mov.b64 %0, {%1, %2};" : "=l"(r) : "f"(lo), "f"(hi));
    return r;
}
static __device__ __forceinline__ void unpack2(ull v, float& lo, float& hi) {
    asm("mov.b64 {%0, %1}, %2;" : "=f"(lo), "=f"(hi) : "l"(v));
}
// d = a*b + c (fresh destination, packed f32x2)
static __device__ __forceinline__ ull ffma2(ull a, ull b, ull c) {
    ull d;
    asm("fma.rn.f32x2 %0, %1, %2, %3;" : "=l"(d) : "l"(a), "l"(b), "l"(c));
    return d;
}
// {lo, hi} -> bf16x2 reg (lo in low 16 bits = even-k element)
static __device__ __forceinline__ uint32_t bf16x2(float lo, float hi) {
    uint32_t r;
    asm("cvt.rn.bf16x2.f32 %0, %1, %2;" : "=r"(r) : "f"(hi), "f"(lo));
    return r;
}

// D += A*B (bf16 m16n8k16, f32 accum, in place)
static __device__ __forceinline__ void mma_acc(float* d, const uint32_t* a,
                                               const uint32_t* b) {
    asm volatile(
        "mma.sync.aligned.m16n8k16.row.col.f32.bf16.bf16.f32 "
        "{%0,%1,%2,%3}, {%4,%5,%6,%7}, {%8,%9}, {%0,%1,%2,%3};"
        : "+f"(d[0]), "+f"(d[1]), "+f"(d[2]), "+f"(d[3])
        : "r"(a[0]), "r"(a[1]), "r"(a[2]), "r"(a[3]), "r"(b[0]), "r"(b[1]));
}
// D = A*B + {c0,c1,c0,c1}  (bias init: writes D fresh)
static __device__ __forceinline__ void mma_bias(float* d, const uint32_t* a,
                                                const uint32_t* b,
                                                float c0, float c1) {
    asm volatile(
        "mma.sync.aligned.m16n8k16.row.col.f32.bf16.bf16.f32 "
        "{%0,%1,%2,%3}, {%4,%5,%6,%7}, {%8,%9}, {%10,%11,%10,%11};"
        : "=f"(d[0]), "=f"(d[1]), "=f"(d[2]), "=f"(d[3])
        : "r"(a[0]), "r"(a[1]), "r"(a[2]), "r"(a[3]), "r"(b[0]), "r"(b[1]),
          "f"(c0), "f"(c1));
}

// softplus(x) = max(x,0) + ln2 * lg2(1 + 2^(-|x|*log2e)), MUFU approx
static __device__ __forceinline__ float softplus_fast(float x) {
    float t, l;
    const float nax = -fabsf(x) * 1.442695041f;
    asm("ex2.approx.f32 %0, %1;" : "=f"(t) : "f"(nax));
    asm("lg2.approx.f32 %0, %1;" : "=f"(l) : "f"(t + 1.0f));
    return fmaxf(x, 0.0f) + 0.693147181f * l;
}

__global__ void __launch_bounds__(TPB)
lf_mma9_kernel(const float* __restrict__ weights,
               const float* __restrict__ distances,
               const float* __restrict__ W1,
               const float* __restrict__ b1,
               const float* __restrict__ W2,
               const float* __restrict__ b2,
               const float* __restrict__ W3,
               const float* __restrict__ b3,
               float* __restrict__ out)
{
    __shared__ float  sW[NB * NN];    // all weights (16 KB)
    __shared__ float4 sW1[NH];        // {W1[0,h], W1[1,h], W1[2,h], b1[h]}
    __shared__ float2 sBW[NH];        // {b2[k], W3[k]}
    __shared__ float  sW2[NH * NH];   // W2[h][n] row-major

    const int tid  = threadIdx.x;
    const int wid  = tid >> 5;
    const int lane = tid & 31;
    const int q    = lane & 3;        // quad column
    const int g    = lane >> 2;       // row / B-col position

    for (int x = tid; x < (NB * NN) / 4; x += TPB)
        ((float4*)sW)[x] = ((const float4*)weights)[x];
    for (int x = tid; x < (NH * NH) / 4; x += TPB)
        ((float4*)sW2)[x] = ((const float4*)W2)[x];
    if (tid < NH) {
        sW1[tid] = make_float4(W1[tid], W1[NH + tid], W1[2 * NH + tid], b1[tid]);
        sBW[tid] = make_float2(b2[tid], W3[tid]);
    }
    __syncthreads();

    // ---- loop-invariant register state ----
    // B fragments (bf16x2): bf[kt][nt] = cols n=8nt+g, k pairs {2q,2q+1}(+16kt)
    // and {2q+8,2q+9}(+16kt)
    uint32_t bf[2][4][2];
#pragma unroll
    for (int kt = 0; kt < 2; kt++)
#pragma unroll
        for (int nt = 0; nt < 4; nt++) {
            const int n = 8 * nt + g;
            bf[kt][nt][0] = bf16x2(sW2[(16 * kt + 2 * q)     * NH + n],
                                   sW2[(16 * kt + 2 * q + 1) * NH + n]);
            bf[kt][nt][1] = bf16x2(sW2[(16 * kt + 2 * q + 8) * NH + n],
                                   sW2[(16 * kt + 2 * q + 9) * NH + n]);
        }
    // W1 coefficient pairs for this thread's h-columns: pair p covers
    // h = {2q + 8p, 2q + 8p + 1}, p = 0..3
    ull X2[4], Y2[4], Z2[4], Wb2[4];
#pragma unroll
    for (int p = 0; p < 4; p++) {
        const float4 c0 = sW1[2 * q + 8 * p];
        const float4 c1 = sW1[2 * q + 8 * p + 1];
        X2[p]  = pack2(c0.x, c1.x);
        Y2[p]  = pack2(c0.y, c1.y);
        Z2[p]  = pack2(c0.z, c1.z);
        Wb2[p] = pack2(c0.w, c1.w);
    }
    float2 bw[8];                     // {b2, W3} at n = 8nt + 2q + {0,1}
#pragma unroll
    for (int nt = 0; nt < 4; nt++) {
        bw[2 * nt]     = sBW[8 * nt + 2 * q];
        bw[2 * nt + 1] = sBW[8 * nt + 2 * q + 1];
    }
    const float b3v = b3[0];

    const int gw     = blockIdx.x * 4 + wid;
    const int stride = GRID * 4;

    // prefetch first tile's distances (flat elem offset = t*32 + g)
    float d0 = 0.f, d1 = 0.f, d2 = 0.f, d3 = 0.f;
    if (gw < NWT2) {
        const unsigned off = ((unsigned)gw << 5) + g;
        d0 = __ldcs(distances + off);
        d1 = __ldcs(distances + off + 8);
        d2 = __ldcs(distances + off + 16);
        d3 = __ldcs(distances + off + 24);
    }

    for (int t = gw; t < NWT2; t += stride) {
        const unsigned off = ((unsigned)t << 5) + g;

        const float wi = sW[t >> 5];
        const unsigned jbase = ((unsigned)(t >> 15) << 10) + ((t & 31) << 5) + g;
        const float wj0 = sW[jbase];
        const float wj1 = sW[jbase + 8];
        const float wj2 = sW[jbase + 16];
        const float wj3 = sW[jbase + 24];

        // packed broadcast operands for the 4 rows this thread touches
        const ull wip   = pack2(wi, wi);
        const ull wjp[4] = { pack2(wj0, wj0), pack2(wj1, wj1),
                             pack2(wj2, wj2), pack2(wj3, wj3) };
        const ull dp[4]  = { pack2(d0, d0), pack2(d1, d1),
                             pack2(d2, d2), pack2(d3, d3) };

        // ai pairs: ai2[p] = W1[0]-pair * wi + b1-pair
        ull ai2[4];
#pragma unroll
        for (int p = 0; p < 4; p++) ai2[p] = ffma2(X2[p], wip, Wb2[p]);

        float accA[4][4], accB[4][4];

        // ---- kt loop: build 8 bf16x2 A-frags, fire 8 MMAs ----
#pragma unroll
        for (int kt = 0; kt < 2; kt++) {
            const int p0 = 2 * kt;       // cols {2q, 2q+1} + 16kt
            const int p1 = 2 * kt + 1;   // cols {2q+8, 2q+9} + 16kt
            uint32_t afA[4], afB[4];
#pragma unroll
            for (int r = 0; r < 4; r++) {            // rows: g, g+8 per tile
                // pair p0
                ull t0 = ffma2(Y2[p0], wjp[r], ai2[p0]);
                t0 = ffma2(Z2[p0], dp[r], t0);
                float lo, hi;
                unpack2(t0, lo, hi);
                const uint32_t v0 = bf16x2(fmaxf(lo, 0.f), fmaxf(hi, 0.f));
                // pair p1
                ull t1 = ffma2(Y2[p1], wjp[r], ai2[p1]);
                t1 = ffma2(Z2[p1], dp[r], t1);
                unpack2(t1, lo, hi);
                const uint32_t v1 = bf16x2(fmaxf(lo, 0.f), fmaxf(hi, 0.f));
                // r0,r1 -> tile A (a0/a1 = pair p0, a2/a3 = pair p1)
                // r2,r3 -> tile B
                if (r < 2) { afA[r] = v0; afA[r + 2] = v1; }
                else       { afB[r - 2] = v0; afB[r] = v1; }
            }
            if (kt == 0) {
#pragma unroll
                for (int nt = 0; nt < 4; nt++) {
                    mma_bias(accA[nt], afA, bf[0][nt], bw[2*nt].x, bw[2*nt+1].x);
                    mma_bias(accB[nt], afB, bf[0][nt], bw[2*nt].x, bw[2*nt+1].x);
                }
            } else {
#pragma unroll
                for (int nt = 0; nt < 4; nt++) {
                    mma_acc(accA[nt], afA, bf[1][nt]);
                    mma_acc(accB[nt], afB, bf[1][nt]);
                }
            }
        }

        // prefetch next tile (hide LDG under epilogue)
        const int tn = t + stride;
        float d0n = 0.f, d1n = 0.f, d2n = 0.f, d3n = 0.f;
        if (tn < NWT2) {
            const unsigned offn = ((unsigned)tn << 5) + g;
            d0n = __ldcs(distances + offn);
            d1n = __ldcs(distances + offn + 8);
            d2n = __ldcs(distances + offn + 16);
            d3n = __ldcs(distances + offn + 24);
        }

        // ---- epilogue: relu . W3, quad reduce, softplus ----
        float s0 = 0.f, s1 = 0.f, s2 = 0.f, s3 = 0.f;
#pragma unroll
        for (int nt = 0; nt < 4; nt++) {
            const float w30 = bw[2 * nt].y;
            const float w31 = bw[2 * nt + 1].y;
            s0 = fmaf(fmaxf(accA[nt][0], 0.f), w30, s0);
            s0 = fmaf(fmaxf(accA[nt][1], 0.f), w31, s0);
            s1 = fmaf(fmaxf(accA[nt][2], 0.f), w30, s1);
            s1 = fmaf(fmaxf(accA[nt][3], 0.f), w31, s1);
            s2 = fmaf(fmaxf(accB[nt][0], 0.f), w30, s2);
            s2 = fmaf(fmaxf(accB[nt][1], 0.f), w31, s2);
            s3 = fmaf(fmaxf(accB[nt][2], 0.f), w30, s3);
            s3 = fmaf(fmaxf(accB[nt][3], 0.f), w31, s3);
        }
        s0 += __shfl_xor_sync(0xffffffffu, s0, 1);
        s1 += __shfl_xor_sync(0xffffffffu, s1, 1);
        s2 += __shfl_xor_sync(0xffffffffu, s2, 1);
        s3 += __shfl_xor_sync(0xffffffffu, s3, 1);
        s0 += __shfl_xor_sync(0xffffffffu, s0, 2);
        s1 += __shfl_xor_sync(0xffffffffu, s1, 2);
        s2 += __shfl_xor_sync(0xffffffffu, s2, 2);
        s3 += __shfl_xor_sync(0xffffffffu, s3, 2);

        if (q == 0) {
            __stcs(out + off,      softplus_fast(s0 + b3v));
            __stcs(out + off + 8,  softplus_fast(s1 + b3v));
            __stcs(out + off + 16, softplus_fast(s2 + b3v));
            __stcs(out + off + 24, softplus_fast(s3 + b3v));
        }

        d0 = d0n; d1 = d1n; d2 = d2n; d3 = d3n;
    }
}

extern "C" void kernel_launch(void* const* d_in, const int* in_sizes, int n_in,
                              void* d_out, int out_size)
{
    const float* weights   = (const float*)d_in[0];
    const float* distances = (const float*)d_in[1];
    const float* W1        = (const float*)d_in[2];
    const float* b1        = (const float*)d_in[3];
    const float* W2        = (const float*)d_in[4];
    const float* b2        = (const float*)d_in[5];
    const float* W3        = (const float*)d_in[6];
    const float* b3        = (const float*)d_in[7];
    float* out             = (float*)d_out;

    lf_mma9_kernel<<<GRID, TPB>>>(weights, distances, W1, b1, W2, b2, W3, b3, out);
}